// round 2
// baseline (speedup 1.0000x reference)
#include <cuda_runtime.h>
#include <math_constants.h>

// Shapes (fixed by the problem)
#define BB   8
#define DD   256
#define TT   2048
#define NE   8192
#define MTOK (BB * TT)        // 16384 tokens
#define BDT  (BB * DD * TT)   // 4194304 z elements

// GEMM tiling
#define TM 64      // tokens per CTA
#define TN 128     // codes per n-tile
#define KC 8       // k-chunk

#define GATHER_BLOCKS 2048

// Device scratch (allocation-free rule: __device__ globals)
__device__ float  g_A[MTOK];          // ||z_t||^2 per token (fp32, like reference)
__device__ float  g_Bsq[NE];          // ||e_n||^2 per code
__device__ int    g_idx[MTOK];        // argmin result
__device__ double g_part[GATHER_BLOCKS]; // per-block loss partials (deterministic reduce)

// --- per-token ||z||^2 ------------------------------------------------------
__global__ void k_prep_A(const float* __restrict__ z) {
    int m = blockIdx.x * 256 + threadIdx.x;   // token id = b*TT + t
    int b = m >> 11;
    int t = m & 2047;
    const float* p = z + (size_t)b * DD * TT + t;
    double s = 0.0;
#pragma unroll 8
    for (int d = 0; d < DD; d++) {
        float v = p[(size_t)d * TT];
        s += (double)v * (double)v;
    }
    g_A[m] = (float)s;
}

// --- per-code ||e||^2 -------------------------------------------------------
__global__ void k_prep_B(const float* __restrict__ emb) {
    int warp = (blockIdx.x * blockDim.x + threadIdx.x) >> 5;
    int lane = threadIdx.x & 31;
    if (warp >= NE) return;
    const float* p = emb + (size_t)warp * DD;
    double s = 0.0;
    for (int d = lane; d < DD; d += 32) {
        float v = p[d];
        s += (double)v * (double)v;
    }
#pragma unroll
    for (int off = 16; off; off >>= 1)
        s += __shfl_down_sync(0xffffffffu, s, off);
    if (lane == 0) g_Bsq[warp] = (float)s;
}

// --- fused GEMM + argmin ----------------------------------------------------
// Each CTA: 64 tokens, full z-tile (256 x 64 fp32 = 64KB) in dynamic smem,
// loops all 8192 codes in 128-wide tiles, K chunked by 8.
// Thread (ty,tx): ty in [0,16) -> 4 tokens, tx in [0,16) -> 8 codes.
__global__ void __launch_bounds__(256, 2)
k_argmin(const float* __restrict__ z, const float* __restrict__ emb) {
    extern __shared__ float Zs[];            // [DD][TM] = 256*64 floats
    __shared__ float Bsh[KC][TN];            // emb k-chunk tile
    __shared__ float Aval[TM];
    __shared__ float rd[TM][16];
    __shared__ int   ri[TM][16];

    const int tid = threadIdx.x;
    const int mb  = blockIdx.x;
    const int t0g = mb * TM;                 // global first token of tile
    const int b   = t0g >> 11;
    const int t0  = t0g & 2047;
    const float* zb = z + (size_t)b * DD * TT + t0;

    // Load whole z tile: Zs[d*TM + tl] = z[b, d, t0+tl]  (coalesced along t)
#pragma unroll 4
    for (int i = tid; i < DD * TM; i += 256) {
        int d  = i >> 6;
        int tl = i & 63;
        Zs[i] = zb[(size_t)d * TT + tl];
    }
    if (tid < TM) Aval[tid] = g_A[t0g + tid];
    __syncthreads();

    const int ty = tid >> 4;
    const int tx = tid & 15;

    float av[4];
#pragma unroll
    for (int i = 0; i < 4; i++) av[i] = Aval[ty * 4 + i];

    float bestd[4];
    int   besti[4];
#pragma unroll
    for (int i = 0; i < 4; i++) { bestd[i] = CUDART_INF_F; besti[i] = 0; }

    const int nlL = tid >> 1;            // 0..127: code row this thread loads
    const int kqL = (tid & 1) * 4;       // 0 or 4: k sub-offset

    for (int n0 = 0; n0 < NE; n0 += TN) {
        float acc[4][8];
#pragma unroll
        for (int i = 0; i < 4; i++)
#pragma unroll
            for (int j = 0; j < 8; j++) acc[i][j] = 0.0f;

        for (int k0 = 0; k0 < DD; k0 += KC) {
            float4 v = *(const float4*)(emb + (size_t)(n0 + nlL) * DD + k0 + kqL);
            __syncthreads();   // protect previous chunk's consumers
            Bsh[kqL + 0][nlL] = v.x;
            Bsh[kqL + 1][nlL] = v.y;
            Bsh[kqL + 2][nlL] = v.z;
            Bsh[kqL + 3][nlL] = v.w;
            __syncthreads();
#pragma unroll
            for (int kc = 0; kc < KC; kc++) {
                float4 a  = *(const float4*)&Zs[(k0 + kc) * TM + ty * 4];
                float4 b0 = *(const float4*)&Bsh[kc][tx * 8];
                float4 b1 = *(const float4*)&Bsh[kc][tx * 8 + 4];
                float aa[4] = {a.x, a.y, a.z, a.w};
                float bb[8] = {b0.x, b0.y, b0.z, b0.w, b1.x, b1.y, b1.z, b1.w};
#pragma unroll
                for (int i = 0; i < 4; i++)
#pragma unroll
                    for (int j = 0; j < 8; j++)
                        acc[i][j] = fmaf(aa[i], bb[j], acc[i][j]);
            }
        }

        // d = (||z||^2 + ||e||^2) - 2*acc  -- same fp32 rounding shape as the
        // reference (x2 is exact; FFMA(acc,-2,t) == fl(t - 2*acc)).
        float4 q0 = *(const float4*)(g_Bsq + n0 + tx * 8);
        float4 q1 = *(const float4*)(g_Bsq + n0 + tx * 8 + 4);
        float bq[8] = {q0.x, q0.y, q0.z, q0.w, q1.x, q1.y, q1.z, q1.w};
#pragma unroll
        for (int i = 0; i < 4; i++) {
#pragma unroll
            for (int j = 0; j < 8; j++) {
                float dv = (av[i] + bq[j]) - 2.0f * acc[i][j];
                // strict < keeps the FIRST (lowest-n) minimum: n ascends in
                // this thread's scan order, matching jnp.argmin tie-break.
                if (dv < bestd[i]) { bestd[i] = dv; besti[i] = n0 + tx * 8 + j; }
            }
        }
    }

    __syncthreads();
#pragma unroll
    for (int i = 0; i < 4; i++) {
        rd[ty * 4 + i][tx] = bestd[i];
        ri[ty * 4 + i][tx] = besti[i];
    }
    __syncthreads();

    // Cross-thread reduce per token: code sets of different tx interleave
    // across n-tiles, so ties need explicit lowest-index resolution.
    if (tid < TM) {
        float bd = rd[tid][0];
        int   bi = ri[tid][0];
#pragma unroll
        for (int x = 1; x < 16; x++) {
            float d2 = rd[tid][x];
            int   i2 = ri[tid][x];
            if (d2 < bd || (d2 == bd && i2 < bi)) { bd = d2; bi = i2; }
        }
        g_idx[t0g + tid] = bi;
    }
}

// --- gather + straight-through output + loss partials ------------------------
__global__ void k_gather(const float* __restrict__ z,
                         const float* __restrict__ emb,
                         float* __restrict__ out) {
    __shared__ double red[256];
    const size_t stride = (size_t)GATHER_BLOCKS * 256;
    double ls = 0.0;
    for (size_t i = (size_t)blockIdx.x * 256 + threadIdx.x; i < (size_t)BDT; i += stride) {
        int t  = (int)(i & 2047);
        int bd = (int)(i >> 11);
        int d  = bd & 255;
        int b  = bd >> 8;
        int m  = (b << 11) + t;
        int code = g_idx[m];
        float zp   = z[i];
        float zq   = emb[(size_t)code * DD + d];
        float diff = zq - zp;                  // fl(zq - zp), as in reference
        out[i] = zp + diff;                    // STE: fl(zp + fl(zq - zp))
        float df2 = diff * diff;               // fp32 square, as in reference
        ls += (double)df2;
    }
    red[threadIdx.x] = ls;
    __syncthreads();
#pragma unroll
    for (int s = 128; s; s >>= 1) {
        if (threadIdx.x < s) red[threadIdx.x] += red[threadIdx.x + s];
        __syncthreads();
    }
    if (threadIdx.x == 0) g_part[blockIdx.x] = red[0];
}

// --- write idx + loss --------------------------------------------------------
__global__ void k_final(float* __restrict__ out) {
    int i = blockIdx.x * 256 + threadIdx.x;
    if (i < MTOK) out[BDT + 1 + i] = (float)g_idx[i];
    if (blockIdx.x == 0) {
        __shared__ double red[256];
        double s = 0.0;
        for (int j = threadIdx.x; j < GATHER_BLOCKS; j += 256) s += g_part[j];
        red[threadIdx.x] = s;
        __syncthreads();
#pragma unroll
        for (int st = 128; st; st >>= 1) {
            if (threadIdx.x < st) red[threadIdx.x] += red[threadIdx.x + st];
            __syncthreads();
        }
        if (threadIdx.x == 0)
            out[BDT] = (float)(1.25 * red[0] / (double)BDT);
    }
}

extern "C" void kernel_launch(void* const* d_in, const int* in_sizes, int n_in,
                              void* d_out, int out_size) {
    const float* z   = (const float*)d_in[0];   // [B, D, T] fp32
    const float* emb = (const float*)d_in[1];   // [n_e, D] fp32
    float* out = (float*)d_out;

    // 64KB dynamic smem for the z tile (attribute set is idempotent & capture-safe)
    cudaFuncSetAttribute(k_argmin, cudaFuncAttributeMaxDynamicSharedMemorySize,
                         DD * TM * (int)sizeof(float));

    k_prep_A<<<MTOK / 256, 256>>>(z);
    k_prep_B<<<NE / 8, 256>>>(emb);
    k_argmin<<<MTOK / TM, 256, DD * TM * sizeof(float)>>>(z, emb);
    k_gather<<<GATHER_BLOCKS, 256>>>(z, emb, out);
    k_final<<<MTOK / 256, 256>>>(out);
}

// round 4
// speedup vs baseline: 4.7302x; 4.7302x over previous
#include <cuda_runtime.h>
#include <cuda_fp16.h>
#include <cstdint>
#include <math_constants.h>

// ---------------------------------------------------------------------------
#define BB   8
#define DD   256
#define TT   2048
#define NE   8192
#define MTOK (BB * TT)        // 16384
#define BDT  (BB * DD * TT)   // 4194304

#define MT    128             // tokens per CTA
#define NTILE 128             // codes per N-tile
#define NTILES (NE / NTILE)   // 64
#define KCH   64              // K chunk
#define TOTCH (NTILES * (DD / KCH))  // 256 chunks

#define GATHER_BLOCKS 2048
#define LO_SCALE   4096.0f
#define LO_UNSCALE 2.44140625e-4f    // 2^-12

// ---------------------------------------------------------------------------
__device__ float  g_A[MTOK];
__device__ float  g_Bsq[NE];
__device__ int    g_idx[MTOK];
__device__ double g_part[GATHER_BLOCKS];
__device__ __half g_Zh[(size_t)MTOK * DD];   // z hi split  [m][k]
__device__ __half g_Zl[(size_t)MTOK * DD];   // z lo * 2^12
__device__ __half g_Eh[(size_t)NE * DD];     // emb hi      [n][k]
__device__ __half g_El[(size_t)NE * DD];     // emb lo * 2^12

// ---------------------------------------------------------------------------
__device__ __forceinline__ uint32_t smem_u32(const void* p) {
    uint32_t a;
    asm("{ .reg .u64 t; cvta.to.shared.u64 t, %1; cvt.u32.u64 %0, t; }"
        : "=r"(a) : "l"(p));
    return a;
}
__device__ __forceinline__ void cp16(uint32_t dst, const void* src) {
    asm volatile("cp.async.cg.shared.global [%0], [%1], 16;" :: "r"(dst), "l"(src));
}
__device__ __forceinline__ void cp_commit() {
    asm volatile("cp.async.commit_group;" ::: "memory");
}
template <int N>
__device__ __forceinline__ void cp_wait() {
    asm volatile("cp.async.wait_group %0;" :: "n"(N) : "memory");
}
__device__ __forceinline__ void ldsm4(uint32_t* r, uint32_t a) {
    asm volatile("ldmatrix.sync.aligned.m8n8.x4.shared.b16 {%0,%1,%2,%3}, [%4];"
        : "=r"(r[0]), "=r"(r[1]), "=r"(r[2]), "=r"(r[3]) : "r"(a));
}
__device__ __forceinline__ void mma16816(float* d, const uint32_t* a, const uint32_t* b) {
    asm volatile("mma.sync.aligned.m16n8k16.row.col.f32.f16.f16.f32 "
        "{%0,%1,%2,%3}, {%4,%5,%6,%7}, {%8,%9}, {%0,%1,%2,%3};"
        : "+f"(d[0]), "+f"(d[1]), "+f"(d[2]), "+f"(d[3])
        : "r"(a[0]), "r"(a[1]), "r"(a[2]), "r"(a[3]), "r"(b[0]), "r"(b[1]));
}

// smem layout (from 1KB-aligned base sb):
//  A: zh [0,64K), zl [64K,128K)   rows 128 x 512B, XOR16-swizzled by row&7
//  B: 2 stages x (eh 16K + el 16K) at OFF_B
#define OFF_B 131072
#define DYN_SMEM (1024 + OFF_B + 2 * 32768)

__device__ __forceinline__ uint32_t addrA(uint32_t sb, int split, int row, int k) {
    return sb + split * 65536 + row * 512 + ((k * 2) ^ ((row & 7) << 4));
}
__device__ __forceinline__ uint32_t addrB(uint32_t sb, int stage, int half, int row, int k) {
    return sb + OFF_B + stage * 32768 + half * 16384 + row * 128
         + ((k * 2) ^ ((row & 7) << 4));
}

// ---------------------------------------------------------------------------
// Prep kernels
__global__ void k_prep_A(const float* __restrict__ z) {
    int m = blockIdx.x * 256 + threadIdx.x;
    int b = m >> 11, t = m & 2047;
    const float* p = z + (size_t)b * DD * TT + t;
    double s = 0.0;
#pragma unroll 8
    for (int d = 0; d < DD; d++) { float v = p[(size_t)d * TT]; s += (double)v * v; }
    g_A[m] = (float)s;
}

__global__ void k_prep_B(const float* __restrict__ emb) {
    int warp = (blockIdx.x * blockDim.x + threadIdx.x) >> 5;
    int lane = threadIdx.x & 31;
    if (warp >= NE) return;
    const float* p = emb + (size_t)warp * DD;
    double s = 0.0;
    for (int d = lane; d < DD; d += 32) { float v = p[d]; s += (double)v * v; }
#pragma unroll
    for (int off = 16; off; off >>= 1) s += __shfl_down_sync(0xffffffffu, s, off);
    if (lane == 0) g_Bsq[warp] = (float)s;
}

// z [B,D,T] -> Zh/Zl [m][k] fp16 splits (transpose via smem tile)
__global__ void k_prep_z(const float* __restrict__ z) {
    __shared__ float tile[64][65];
    int b = blockIdx.z, d0 = blockIdx.y * 64, t0 = blockIdx.x * 64;
    int tx = threadIdx.x & 63, ty = threadIdx.x >> 6;
    for (int r = ty; r < 64; r += 4)
        tile[r][tx] = z[((size_t)b * DD + d0 + r) * TT + t0 + tx];
    __syncthreads();
    for (int r = ty; r < 64; r += 4) {
        size_t m = (size_t)b * TT + t0 + r;
        float x = tile[tx][r];
        __half h = __float2half(x);
        g_Zh[m * DD + d0 + tx] = h;
        g_Zl[m * DD + d0 + tx] = __float2half((x - __half2float(h)) * LO_SCALE);
    }
}

__global__ void k_prep_emb(const float* __restrict__ emb) {
    size_t i = (size_t)blockIdx.x * 256 + threadIdx.x;
    float x = emb[i];
    __half h = __float2half(x);
    g_Eh[i] = h;
    g_El[i] = __float2half((x - __half2float(h)) * LO_SCALE);
}

// ---------------------------------------------------------------------------
// Main: fp16-split HMMA GEMM + fused argmin.
// 512 threads = 4(M) x 4(N) warps; warp tile 32x32 (2 m16-tiles x 4 n8-tiles).
__global__ void __launch_bounds__(512, 1)
k_mma() {
    extern __shared__ char smem_raw[];
    const uint32_t raw = smem_u32(smem_raw);
    const uint32_t sb  = (raw + 1023) & ~1023u;

    const int tid  = threadIdx.x;
    const int wid  = tid >> 5, lane = tid & 31;
    const int wm   = wid & 3,  wn   = wid >> 2;
    const int t0g  = blockIdx.x * MT;

    // ---- issue A loads + chunk 0 (group 0) ----
#pragma unroll
    for (int si = 0; si < 2; si++) {
        const __half* src = (si ? g_Zl : g_Zh) + (size_t)t0g * DD;
#pragma unroll
        for (int j = 0; j < 8; j++) {
            int seg = tid + j * 512;
            int row = seg >> 5, sg = seg & 31;
            cp16(sb + si * 65536 + row * 512 + ((sg * 16) ^ ((row & 7) << 4)),
                 src + (size_t)row * DD + sg * 8);
        }
    }
    // B-chunk issue helper (inlined twice below): chunk i -> tile=i>>2, c=i&3
#define ISSUE_B(I, STAGE) do {                                                \
    int _tile = (I) >> 2, _c = (I) & 3;                                       \
    _Pragma("unroll")                                                         \
    for (int _h = 0; _h < 2; _h++) {                                          \
        const __half* _src = (_h ? g_El : g_Eh)                               \
                           + (size_t)(_tile * NTILE) * DD + _c * KCH;         \
        _Pragma("unroll")                                                     \
        for (int _j = 0; _j < 2; _j++) {                                      \
            int _seg = tid + _j * 512;                                        \
            int _row = _seg >> 3, _sg = _seg & 7;                             \
            cp16(addrB(sb, (STAGE), _h, _row, _sg * 8),                       \
                 _src + (size_t)_row * DD + _sg * 8);                         \
        }                                                                     \
    }                                                                         \
} while (0)

    ISSUE_B(0, 0);
    cp_commit();

    float av[4];
    {
        int r0 = wm * 32 + (lane >> 2);
        av[0] = g_A[t0g + r0];      av[1] = g_A[t0g + r0 + 8];
        av[2] = g_A[t0g + r0 + 16]; av[3] = g_A[t0g + r0 + 24];
    }

    float bestd[4]; int besti[4];
#pragma unroll
    for (int k = 0; k < 4; k++) { bestd[k] = CUDART_INF_F; besti[k] = 0; }

    float acc0[2][4][4], acc1[2][4][4];

    for (int i = 0; i < TOTCH; i++) {
        const int stage = i & 1;
        if (i + 1 < TOTCH) ISSUE_B(i + 1, stage ^ 1);
        cp_commit();
        cp_wait<1>();
        __syncthreads();

        const int tile = i >> 2, c = i & 3;
        if (c == 0) {
#pragma unroll
            for (int mt = 0; mt < 2; mt++)
#pragma unroll
                for (int nt = 0; nt < 4; nt++)
#pragma unroll
                    for (int q = 0; q < 4; q++) {
                        acc0[mt][nt][q] = 0.0f; acc1[mt][nt][q] = 0.0f;
                    }
        }

        // 4 x k16 steps over this 64-deep chunk
#pragma unroll
        for (int k16 = 0; k16 < 4; k16++) {
            const int kloc  = k16 * 16;
            const int kglob = c * KCH + kloc;

            uint32_t ah[2][4], al[2][4];
#pragma unroll
            for (int mt = 0; mt < 2; mt++) {
                const int mrow = wm * 32 + mt * 16;
                const int row  = mrow + (lane & 15);
                const int col  = kglob + ((lane >> 4) << 3);
                ldsm4(ah[mt], addrA(sb, 0, row, col));
                ldsm4(al[mt], addrA(sb, 1, row, col));
            }
            uint32_t beh[4][2], bel[4][2];
#pragma unroll
            for (int ntp = 0; ntp < 2; ntp++) {
                const int nrow = wn * 32 + ntp * 16;
                const int g    = lane >> 3;
                const int row  = nrow + ((g >> 1) << 3) + (lane & 7);
                const int col  = kloc + ((g & 1) << 3);
                uint32_t r4[4];
                ldsm4(r4, addrB(sb, stage, 0, row, col));
                beh[ntp * 2][0] = r4[0]; beh[ntp * 2][1] = r4[1];
                beh[ntp * 2 + 1][0] = r4[2]; beh[ntp * 2 + 1][1] = r4[3];
                ldsm4(r4, addrB(sb, stage, 1, row, col));
                bel[ntp * 2][0] = r4[0]; bel[ntp * 2][1] = r4[1];
                bel[ntp * 2 + 1][0] = r4[2]; bel[ntp * 2 + 1][1] = r4[3];
            }
#pragma unroll
            for (int mt = 0; mt < 2; mt++)
#pragma unroll
                for (int nt = 0; nt < 4; nt++) {
                    mma16816(acc0[mt][nt], ah[mt], beh[nt]);   // zh*eh
                    mma16816(acc1[mt][nt], ah[mt], bel[nt]);   // zh*el'
                    mma16816(acc1[mt][nt], al[mt], beh[nt]);   // zl'*eh
                }
        }

        if (c == 3) {
            // epilogue: d = fl(fl(av+bq) - 2*acc), running first-min argmin
            const int nb = tile * NTILE + wn * 32 + (lane & 3) * 2;
#pragma unroll
            for (int nt = 0; nt < 4; nt++) {
                const int n0 = nb + nt * 8;
                const float bq0 = __ldg(&g_Bsq[n0]);
                const float bq1 = __ldg(&g_Bsq[n0 + 1]);
#pragma unroll
                for (int mt = 0; mt < 2; mt++) {
                    const float a00 = acc0[mt][nt][0] + acc1[mt][nt][0] * LO_UNSCALE;
                    const float a01 = acc0[mt][nt][1] + acc1[mt][nt][1] * LO_UNSCALE;
                    const float a10 = acc0[mt][nt][2] + acc1[mt][nt][2] * LO_UNSCALE;
                    const float a11 = acc0[mt][nt][3] + acc1[mt][nt][3] * LO_UNSCALE;
                    const int r0 = mt * 2, r1 = mt * 2 + 1;
                    float d;
                    d = fmaf(-2.0f, a00, av[r0] + bq0);
                    if (d < bestd[r0]) { bestd[r0] = d; besti[r0] = n0; }
                    d = fmaf(-2.0f, a01, av[r0] + bq1);
                    if (d < bestd[r0]) { bestd[r0] = d; besti[r0] = n0 + 1; }
                    d = fmaf(-2.0f, a10, av[r1] + bq0);
                    if (d < bestd[r1]) { bestd[r1] = d; besti[r1] = n0; }
                    d = fmaf(-2.0f, a11, av[r1] + bq1);
                    if (d < bestd[r1]) { bestd[r1] = d; besti[r1] = n0 + 1; }
                }
            }
        }
        __syncthreads();
    }

    // ---- cross-lane reduce (the 4 lanes sharing each row) ----
#pragma unroll
    for (int k = 0; k < 4; k++) {
#pragma unroll
        for (int off = 1; off <= 2; off <<= 1) {
            float od = __shfl_xor_sync(0xffffffffu, bestd[k], off);
            int   oi = __shfl_xor_sync(0xffffffffu, besti[k], off);
            if (od < bestd[k] || (od == bestd[k] && oi < besti[k])) {
                bestd[k] = od; besti[k] = oi;
            }
        }
    }
    cp_wait<0>();
    __syncthreads();
    float* sd = (float*)(smem_raw + (sb - raw) + OFF_B);
    int*   si = (int*)(sd + 512);
    if ((lane & 3) == 0) {
        const int rb = wm * 32 + (lane >> 2);
#pragma unroll
        for (int k = 0; k < 4; k++) {
            const int row = rb + k * 8;    // k = mt*2+h -> offsets 0,8,16,24
            sd[row * 4 + wn] = bestd[k];
            si[row * 4 + wn] = besti[k];
        }
    }
    __syncthreads();
    if (tid < MT) {
        float bd = sd[tid * 4]; int bi = si[tid * 4];
#pragma unroll
        for (int x = 1; x < 4; x++) {
            float d2 = sd[tid * 4 + x]; int i2 = si[tid * 4 + x];
            if (d2 < bd || (d2 == bd && i2 < bi)) { bd = d2; bi = i2; }
        }
        g_idx[t0g + tid] = bi;
    }
#undef ISSUE_B
}

// ---------------------------------------------------------------------------
// Gather + STE + loss (proven bit-exact in R1)
__global__ void k_gather(const float* __restrict__ z,
                         const float* __restrict__ emb,
                         float* __restrict__ out) {
    __shared__ double red[256];
    const size_t stride = (size_t)GATHER_BLOCKS * 256;
    double ls = 0.0;
    for (size_t i = (size_t)blockIdx.x * 256 + threadIdx.x; i < (size_t)BDT; i += stride) {
        int t = (int)(i & 2047);
        int bd = (int)(i >> 11);
        int d = bd & 255, b = bd >> 8;
        int code = g_idx[(b << 11) + t];
        float zp = z[i];
        float zq = emb[(size_t)code * DD + d];
        float diff = zq - zp;
        out[i] = zp + diff;
        ls += (double)(diff * diff);
    }
    red[threadIdx.x] = ls;
    __syncthreads();
#pragma unroll
    for (int s = 128; s; s >>= 1) {
        if (threadIdx.x < s) red[threadIdx.x] += red[threadIdx.x + s];
        __syncthreads();
    }
    if (threadIdx.x == 0) g_part[blockIdx.x] = red[0];
}

__global__ void k_final(float* __restrict__ out) {
    int i = blockIdx.x * 256 + threadIdx.x;
    if (i < MTOK) out[BDT + 1 + i] = (float)g_idx[i];
    if (blockIdx.x == 0) {
        __shared__ double red[256];
        double s = 0.0;
        for (int j = threadIdx.x; j < GATHER_BLOCKS; j += 256) s += g_part[j];
        red[threadIdx.x] = s;
        __syncthreads();
#pragma unroll
        for (int st = 128; st; st >>= 1) {
            if (threadIdx.x < st) red[threadIdx.x] += red[threadIdx.x + st];
            __syncthreads();
        }
        if (threadIdx.x == 0) out[BDT] = (float)(1.25 * red[0] / (double)BDT);
    }
}

// ---------------------------------------------------------------------------
extern "C" void kernel_launch(void* const* d_in, const int* in_sizes, int n_in,
                              void* d_out, int out_size) {
    const float* z   = (const float*)d_in[0];
    const float* emb = (const float*)d_in[1];
    float* out = (float*)d_out;

    cudaFuncSetAttribute(k_mma, cudaFuncAttributeMaxDynamicSharedMemorySize, DYN_SMEM);

    k_prep_A<<<MTOK / 256, 256>>>(z);
    k_prep_B<<<NE / 8, 256>>>(emb);
    k_prep_z<<<dim3(TT / 64, DD / 64, BB), 256>>>(z);
    k_prep_emb<<<NE * DD / 256, 256>>>(emb);
    k_mma<<<MTOK / MT, 512, DYN_SMEM>>>();
    k_gather<<<GATHER_BLOCKS, 256>>>(z, emb, out);
    k_final<<<MTOK / 256, 256>>>(out);
}

// round 5
// speedup vs baseline: 5.2295x; 1.1056x over previous
#include <cuda_runtime.h>
#include <cuda_fp16.h>
#include <cstdint>
#include <math_constants.h>

// ---------------------------------------------------------------------------
#define BB   8
#define DD   256
#define TT   2048
#define NE   8192
#define MTOK (BB * TT)        // 16384
#define BDT  (BB * DD * TT)   // 4194304

#define MT    128             // tokens per tile
#define NTILE 128             // codes per N-tile
#define NBLK  8               // n-blocks per token tile (1024 codes each)
#define NUNITS (MTOK / MT * NBLK)   // 1024 work units
#define NCTA  148
#define KCH   64

#define GATHER_BLOCKS 2048
#define LO_SCALE   4096.0f
#define LO_UNSCALE 2.44140625e-4f    // 2^-12

// ---------------------------------------------------------------------------
__device__ float  g_A[MTOK];
__device__ float  g_Bsq[NE];
__device__ int    g_idx[MTOK];
__device__ double g_part[GATHER_BLOCKS];
__device__ __half g_Zh[(size_t)MTOK * DD];
__device__ __half g_Zl[(size_t)MTOK * DD];
__device__ __half g_Eh[(size_t)NE * DD];
__device__ __half g_El[(size_t)NE * DD];
__device__ float  g_pd[(size_t)MTOK * NBLK * 4];   // partial best-d
__device__ int    g_pi[(size_t)MTOK * NBLK * 4];   // partial best-i

// ---------------------------------------------------------------------------
__device__ __forceinline__ uint32_t smem_u32(const void* p) {
    uint32_t a;
    asm("{ .reg .u64 t; cvta.to.shared.u64 t, %1; cvt.u32.u64 %0, t; }"
        : "=r"(a) : "l"(p));
    return a;
}
__device__ __forceinline__ void cp16(uint32_t dst, const void* src) {
    asm volatile("cp.async.cg.shared.global [%0], [%1], 16;" :: "r"(dst), "l"(src));
}
__device__ __forceinline__ void cp_commit() {
    asm volatile("cp.async.commit_group;" ::: "memory");
}
template <int N>
__device__ __forceinline__ void cp_wait() {
    asm volatile("cp.async.wait_group %0;" :: "n"(N) : "memory");
}
__device__ __forceinline__ void ldsm4(uint32_t* r, uint32_t a) {
    asm volatile("ldmatrix.sync.aligned.m8n8.x4.shared.b16 {%0,%1,%2,%3}, [%4];"
        : "=r"(r[0]), "=r"(r[1]), "=r"(r[2]), "=r"(r[3]) : "r"(a));
}
__device__ __forceinline__ void mma16816(float* d, const uint32_t* a, const uint32_t* b) {
    asm volatile("mma.sync.aligned.m16n8k16.row.col.f32.f16.f16.f32 "
        "{%0,%1,%2,%3}, {%4,%5,%6,%7}, {%8,%9}, {%0,%1,%2,%3};"
        : "+f"(d[0]), "+f"(d[1]), "+f"(d[2]), "+f"(d[3])
        : "r"(a[0]), "r"(a[1]), "r"(a[2]), "r"(a[3]), "r"(b[0]), "r"(b[1]));
}

// smem: A zh [0,64K) zl [64K,128K); B 2 stages x (eh 16K + el 16K) at OFF_B
#define OFF_B 131072
#define DYN_SMEM (1024 + OFF_B + 2 * 32768)

__device__ __forceinline__ uint32_t addrA(uint32_t sb, int split, int row, int k) {
    return sb + split * 65536 + row * 512 + ((k * 2) ^ ((row & 7) << 4));
}
__device__ __forceinline__ uint32_t addrB(uint32_t sb, int stage, int half, int row, int k) {
    return sb + OFF_B + stage * 32768 + half * 16384 + row * 128
         + ((k * 2) ^ ((row & 7) << 4));
}

// ---------------------------------------------------------------------------
__global__ void k_prep_A(const float* __restrict__ z) {
    int m = blockIdx.x * 256 + threadIdx.x;
    int b = m >> 11, t = m & 2047;
    const float* p = z + (size_t)b * DD * TT + t;
    double s = 0.0;
#pragma unroll 8
    for (int d = 0; d < DD; d++) { float v = p[(size_t)d * TT]; s += (double)v * v; }
    g_A[m] = (float)s;
}

// z [B,D,T] -> Zh/Zl [m][k] fp16 splits (transpose via smem tile)
__global__ void k_prep_z(const float* __restrict__ z) {
    __shared__ float tile[64][65];
    int b = blockIdx.z, d0 = blockIdx.y * 64, t0 = blockIdx.x * 64;
    int tx = threadIdx.x & 63, ty = threadIdx.x >> 6;
    for (int r = ty; r < 64; r += 4)
        tile[r][tx] = z[((size_t)b * DD + d0 + r) * TT + t0 + tx];
    __syncthreads();
    for (int r = ty; r < 64; r += 4) {
        size_t m = (size_t)b * TT + t0 + r;
        float x = tile[tx][r];
        __half h = __float2half(x);
        g_Zh[m * DD + d0 + tx] = h;
        g_Zl[m * DD + d0 + tx] = __float2half((x - __half2float(h)) * LO_SCALE);
    }
}

// emb splits + ||e||^2 fused: one warp per code row
__global__ void k_prep_emb(const float* __restrict__ emb) {
    int row  = blockIdx.x * 8 + (threadIdx.x >> 5);
    int lane = threadIdx.x & 31;
    const float* p = emb + (size_t)row * DD;
    double s = 0.0;
#pragma unroll
    for (int it = 0; it < 8; it++) {
        int d = it * 32 + lane;
        float x = p[d];
        __half h = __float2half(x);
        g_Eh[(size_t)row * DD + d] = h;
        g_El[(size_t)row * DD + d] = __float2half((x - __half2float(h)) * LO_SCALE);
        s += (double)x * x;
    }
#pragma unroll
    for (int off = 16; off; off >>= 1) s += __shfl_down_sync(0xffffffffu, s, off);
    if (lane == 0) g_Bsq[row] = (float)s;
}

// ---------------------------------------------------------------------------
// Persistent GEMM + fused argmin. 148 CTAs x 512 threads (4x4 warps, 32x32).
// Unit u: token tile (u>>3), n-block (u&7) of 1024 codes (8 NTILEs, 32 chunks).
__global__ void __launch_bounds__(512, 1)
k_mma() {
    extern __shared__ char smem_raw[];
    const uint32_t raw = smem_u32(smem_raw);
    const uint32_t sb  = (raw + 1023) & ~1023u;

    const int tid  = threadIdx.x;
    const int wid  = tid >> 5, lane = tid & 31;
    const int wm   = wid & 3,  wn   = wid >> 2;

    const int u0 = (int)(((long long)blockIdx.x * NUNITS) / NCTA);
    const int u1 = (int)(((long long)(blockIdx.x + 1) * NUNITS) / NCTA);

#define ISSUE_B(J, STAGE, NBASE) do {                                         \
    int _tg = (NBASE) + ((J) >> 2), _c = (J) & 3;                             \
    _Pragma("unroll")                                                         \
    for (int _h = 0; _h < 2; _h++) {                                          \
        const __half* _src = (_h ? g_El : g_Eh)                               \
                           + (size_t)(_tg * NTILE) * DD + _c * KCH;           \
        _Pragma("unroll")                                                     \
        for (int _j = 0; _j < 2; _j++) {                                      \
            int _seg = tid + _j * 512;                                        \
            int _row = _seg >> 3, _sg = _seg & 7;                             \
            cp16(addrB(sb, (STAGE), _h, _row, _sg * 8),                       \
                 _src + (size_t)_row * DD + _sg * 8);                         \
        }                                                                     \
    }                                                                         \
} while (0)

    int prev_tile = -1;
    for (int u = u0; u < u1; u++) {
        const int tile0 = u >> 3;          // token tile
        const int nbase = (u & 7) * 8;     // first NTILE index of this n-block
        const int t0g   = tile0 * MT;

        if (tile0 != prev_tile) {
            prev_tile = tile0;
#pragma unroll
            for (int si = 0; si < 2; si++) {
                const __half* src = (si ? g_Zl : g_Zh) + (size_t)t0g * DD;
#pragma unroll
                for (int j = 0; j < 8; j++) {
                    int seg = tid + j * 512;
                    int row = seg >> 5, sg = seg & 31;
                    cp16(sb + si * 65536 + row * 512 + ((sg * 16) ^ ((row & 7) << 4)),
                         src + (size_t)row * DD + sg * 8);
                }
            }
        }
        ISSUE_B(0, 0, nbase);
        cp_commit();

        float av[4];
        {
            int r0 = wm * 32 + (lane >> 2);
            av[0] = g_A[t0g + r0];      av[1] = g_A[t0g + r0 + 8];
            av[2] = g_A[t0g + r0 + 16]; av[3] = g_A[t0g + r0 + 24];
        }
        float bestd[4]; int besti[4];
#pragma unroll
        for (int k = 0; k < 4; k++) { bestd[k] = CUDART_INF_F; besti[k] = 0; }

        cp_wait<0>();
        __syncthreads();

        float acc0[2][4][4], acc1[2][4][4];

        for (int j = 0; j < 32; j++) {
            const int stage = j & 1;
            if (j + 1 < 32) { ISSUE_B(j + 1, stage ^ 1, nbase); cp_commit(); cp_wait<1>(); }
            else            { cp_wait<0>(); }
            __syncthreads();

            const int tileg = nbase + (j >> 2), c = j & 3;
            if (c == 0) {
#pragma unroll
                for (int mt = 0; mt < 2; mt++)
#pragma unroll
                    for (int nt = 0; nt < 4; nt++)
#pragma unroll
                        for (int q = 0; q < 4; q++) {
                            acc0[mt][nt][q] = 0.0f; acc1[mt][nt][q] = 0.0f;
                        }
            }
#pragma unroll
            for (int k16 = 0; k16 < 4; k16++) {
                const int kloc  = k16 * 16;
                const int kglob = c * KCH + kloc;
                uint32_t ah[2][4], al[2][4];
#pragma unroll
                for (int mt = 0; mt < 2; mt++) {
                    const int row = wm * 32 + mt * 16 + (lane & 15);
                    const int col = kglob + ((lane >> 4) << 3);
                    ldsm4(ah[mt], addrA(sb, 0, row, col));
                    ldsm4(al[mt], addrA(sb, 1, row, col));
                }
                uint32_t beh[4][2], bel[4][2];
#pragma unroll
                for (int ntp = 0; ntp < 2; ntp++) {
                    const int g   = lane >> 3;
                    const int row = wn * 32 + ntp * 16 + ((g >> 1) << 3) + (lane & 7);
                    const int col = kloc + ((g & 1) << 3);
                    uint32_t r4[4];
                    ldsm4(r4, addrB(sb, stage, 0, row, col));
                    beh[ntp * 2][0] = r4[0]; beh[ntp * 2][1] = r4[1];
                    beh[ntp * 2 + 1][0] = r4[2]; beh[ntp * 2 + 1][1] = r4[3];
                    ldsm4(r4, addrB(sb, stage, 1, row, col));
                    bel[ntp * 2][0] = r4[0]; bel[ntp * 2][1] = r4[1];
                    bel[ntp * 2 + 1][0] = r4[2]; bel[ntp * 2 + 1][1] = r4[3];
                }
#pragma unroll
                for (int mt = 0; mt < 2; mt++)
#pragma unroll
                    for (int nt = 0; nt < 4; nt++) {
                        mma16816(acc0[mt][nt], ah[mt], beh[nt]);
                        mma16816(acc1[mt][nt], ah[mt], bel[nt]);
                        mma16816(acc1[mt][nt], al[mt], beh[nt]);
                    }
            }

            if (c == 3) {
                const int nb = tileg * NTILE + wn * 32 + (lane & 3) * 2;
#pragma unroll
                for (int nt = 0; nt < 4; nt++) {
                    const int n0 = nb + nt * 8;
                    const float bq0 = __ldg(&g_Bsq[n0]);
                    const float bq1 = __ldg(&g_Bsq[n0 + 1]);
#pragma unroll
                    for (int mt = 0; mt < 2; mt++) {
                        const float a00 = acc0[mt][nt][0] + acc1[mt][nt][0] * LO_UNSCALE;
                        const float a01 = acc0[mt][nt][1] + acc1[mt][nt][1] * LO_UNSCALE;
                        const float a10 = acc0[mt][nt][2] + acc1[mt][nt][2] * LO_UNSCALE;
                        const float a11 = acc0[mt][nt][3] + acc1[mt][nt][3] * LO_UNSCALE;
                        const int r0 = mt * 2, r1 = mt * 2 + 1;
                        float d;
                        d = fmaf(-2.0f, a00, av[r0] + bq0);
                        if (d < bestd[r0]) { bestd[r0] = d; besti[r0] = n0; }
                        d = fmaf(-2.0f, a01, av[r0] + bq1);
                        if (d < bestd[r0]) { bestd[r0] = d; besti[r0] = n0 + 1; }
                        d = fmaf(-2.0f, a10, av[r1] + bq0);
                        if (d < bestd[r1]) { bestd[r1] = d; besti[r1] = n0; }
                        d = fmaf(-2.0f, a11, av[r1] + bq1);
                        if (d < bestd[r1]) { bestd[r1] = d; besti[r1] = n0 + 1; }
                    }
                }
            }
            __syncthreads();
        }

        // cross-lane reduce within the quad sharing each token row
#pragma unroll
        for (int k = 0; k < 4; k++) {
#pragma unroll
            for (int off = 1; off <= 2; off <<= 1) {
                float od = __shfl_xor_sync(0xffffffffu, bestd[k], off);
                int   oi = __shfl_xor_sync(0xffffffffu, besti[k], off);
                if (od < bestd[k] || (od == bestd[k] && oi < besti[k])) {
                    bestd[k] = od; besti[k] = oi;
                }
            }
        }
        if ((lane & 3) == 0) {
            const int rb = wm * 32 + (lane >> 2);
#pragma unroll
            for (int k = 0; k < 4; k++) {
                const int row = rb + ((k & 1) ? 8 : 0) + ((k >> 1) ? 16 : 0);
                const size_t o = (size_t)(t0g + row) * (NBLK * 4) + (u & 7) * 4 + wn;
                g_pd[o] = bestd[k];
                g_pi[o] = besti[k];
            }
        }
    }
#undef ISSUE_B
}

// ---------------------------------------------------------------------------
// Lexicographic (d, idx) merge of 32 partials per token — equals global
// first-minimum scan; each partial is already first-min of its subset.
__global__ void k_merge(float* __restrict__ out) {
    int m = blockIdx.x * 256 + threadIdx.x;
    const float* pd = g_pd + (size_t)m * 32;
    const int*   pi = g_pi + (size_t)m * 32;
    float bd = pd[0]; int bi = pi[0];
#pragma unroll
    for (int x = 1; x < 32; x++) {
        float d2 = pd[x]; int i2 = pi[x];
        if (d2 < bd || (d2 == bd && i2 < bi)) { bd = d2; bi = i2; }
    }
    g_idx[m] = bi;
    out[BDT + 1 + m] = (float)bi;
}

// ---------------------------------------------------------------------------
__global__ void k_gather(const float* __restrict__ z,
                         const float* __restrict__ emb,
                         float* __restrict__ out) {
    __shared__ double red[256];
    const size_t stride = (size_t)GATHER_BLOCKS * 256;
    double ls = 0.0;
    for (size_t i = (size_t)blockIdx.x * 256 + threadIdx.x; i < (size_t)BDT; i += stride) {
        int t = (int)(i & 2047);
        int bd = (int)(i >> 11);
        int d = bd & 255, b = bd >> 8;
        int code = g_idx[(b << 11) + t];
        float zp = z[i];
        float zq = emb[(size_t)code * DD + d];
        float diff = zq - zp;
        out[i] = zp + diff;
        ls += (double)(diff * diff);
    }
    red[threadIdx.x] = ls;
    __syncthreads();
#pragma unroll
    for (int s = 128; s; s >>= 1) {
        if (threadIdx.x < s) red[threadIdx.x] += red[threadIdx.x + s];
        __syncthreads();
    }
    if (threadIdx.x == 0) g_part[blockIdx.x] = red[0];
}

__global__ void k_final(float* __restrict__ out) {
    __shared__ double red[256];
    double s = 0.0;
    for (int j = threadIdx.x; j < GATHER_BLOCKS; j += 256) s += g_part[j];
    red[threadIdx.x] = s;
    __syncthreads();
#pragma unroll
    for (int st = 128; st; st >>= 1) {
        if (threadIdx.x < st) red[threadIdx.x] += red[threadIdx.x + st];
        __syncthreads();
    }
    if (threadIdx.x == 0) out[BDT] = (float)(1.25 * red[0] / (double)BDT);
}

// ---------------------------------------------------------------------------
extern "C" void kernel_launch(void* const* d_in, const int* in_sizes, int n_in,
                              void* d_out, int out_size) {
    const float* z   = (const float*)d_in[0];
    const float* emb = (const float*)d_in[1];
    float* out = (float*)d_out;

    cudaFuncSetAttribute(k_mma, cudaFuncAttributeMaxDynamicSharedMemorySize, DYN_SMEM);

    k_prep_A<<<MTOK / 256, 256>>>(z);
    k_prep_z<<<dim3(TT / 64, DD / 64, BB), 256>>>(z);
    k_prep_emb<<<NE / 8, 256>>>(emb);
    k_mma<<<NCTA, 512, DYN_SMEM>>>();
    k_merge<<<MTOK / 256, 256>>>(out);
    k_gather<<<GATHER_BLOCKS, 256>>>(z, emb, out);
    k_final<<<1, 256>>>(out);
}